// round 13
// baseline (speedup 1.0000x reference)
#include <cuda_runtime.h>
#include <cuda_fp16.h>
#include <cstdint>

#define NAG   8
#define BATCH 32768
#define SDIM  128
#define ADIM  16
#define HID   128
#define HEADS 4
#define AD    32

// ---------------- scratch (device globals; no allocation allowed) ----------------
__device__ __half g_sa [(size_t)NAG * BATCH * HID];
__device__ __half g_se [(size_t)NAG * BATCH * HID];
__device__ __half g_Kb [(size_t)NAG * BATCH * HID];
__device__ __half g_Qb [(size_t)NAG * BATCH * HID];
__device__ __half g_Vb [(size_t)NAG * BATCH * HID];
__device__ __half g_oth[(size_t)NAG * BATCH * HID];
__device__ __half g_sth[(size_t)NAG * BATCH * SDIM];
__device__ __half g_ach[(size_t)NAG * BATCH * ADIM];
__device__ __half g_Wet [NAG * 128 * 144];
__device__ __half g_Wst [NAG * 128 * 128];
__device__ __half g_Wkt [128 * 128];
__device__ __half g_Wqt [128 * 128];
__device__ __half g_Wvt [128 * 128];
__device__ __half g_Wc1t[NAG * 128 * 256];

__device__ __forceinline__ unsigned pkh2(float a, float b) {
    __half2 h = __floats2half2_rn(a, b);
    return *(unsigned*)&h;
}

#define SROW 12          // 8 data words (16 halves) + 4 pad; frag banks bijective
#define GSTG 4           // GEMM pipeline stages (prefetch distance 3)
#define CSTG 3           // critic pipeline stages

#define MMA16(acc, a0, a1, a2, a3, b0, b1)                                        \
    asm("mma.sync.aligned.m16n8k16.row.col.f32.f16.f16.f32 "                      \
        "{%0,%1,%2,%3}, {%4,%5,%6,%7}, {%8,%9}, {%0,%1,%2,%3};"                   \
        : "+f"((acc)[0]), "+f"((acc)[1]), "+f"((acc)[2]), "+f"((acc)[3])          \
        : "r"(a0), "r"(a1), "r"(a2), "r"(a3), "r"(b0), "r"(b1))

#define CPA16(dst, src) \
    asm volatile("cp.async.cg.shared.global [%0], [%1], 16;\n" :: "r"(dst), "l"(src))
#define CP_COMMIT()  asm volatile("cp.async.commit_group;\n")
#define CP_WAIT2()   asm volatile("cp.async.wait_group 2;\n")
#define CP_WAIT1()   asm volatile("cp.async.wait_group 1;\n")
#define CP_WAIT0()   asm volatile("cp.async.wait_group 0;\n")

// ---------------- merged prep: input fp16 copies + transposed fp16 weights ---------
__global__ void prep_all(const float* __restrict__ states,
                         const float* __restrict__ actions,
                         const float* __restrict__ We, const float* __restrict__ Ws,
                         const float* __restrict__ Wk, const float* __restrict__ Wq,
                         const float* __restrict__ Wv, const float* __restrict__ Wc1)
{
    size_t i  = (size_t)blockIdx.x * blockDim.x + threadIdx.x;
    size_t ns = (size_t)NAG * BATCH * SDIM / 8;
    size_t na = (size_t)NAG * BATCH * ADIM / 8;
    if (i < ns) {
        const float4* s = (const float4*)states + i * 2;
        float4 a = s[0], b = s[1];
        uint4 u = { pkh2(a.x, a.y), pkh2(a.z, a.w), pkh2(b.x, b.y), pkh2(b.z, b.w) };
        *(uint4*)(g_sth + i * 8) = u;
        return;
    }
    if (i < ns + na) {
        size_t j = i - ns;
        const float4* s = (const float4*)actions + j * 2;
        float4 a = s[0], b = s[1];
        uint4 u = { pkh2(a.x, a.y), pkh2(a.z, a.w), pkh2(b.x, b.y), pkh2(b.z, b.w) };
        *(uint4*)(g_ach + j * 8) = u;
        return;
    }
    long w = (long)(i - ns - na);
    const int nWe = NAG * 128 * 144;
    const int nWs = NAG * 128 * 128;
    const int nH  = 128 * 128;
    const int nWc = NAG * 128 * 256;
    if (w < 0 || w >= nWe + nWs + 3 * nH + nWc) return;
    int iw = (int)w;
    if (iw < nWe) {
        int n = iw / (128 * 144), r = iw % (128 * 144);
        int c = r / 144, k = r % 144;
        g_Wet[iw] = __float2half_rn(We[((size_t)n * 144 + k) * 128 + c]);
    } else if (iw < nWe + nWs) {
        int j = iw - nWe;
        int n = j / (128 * 128), r = j % (128 * 128);
        int c = r / 128, k = r % 128;
        g_Wst[j] = __float2half_rn(Ws[((size_t)n * 128 + k) * 128 + c]);
    } else if (iw < nWe + nWs + 3 * nH) {
        int j = iw - nWe - nWs;
        int which = j / nH, r = j % nH;
        int c = r / 128, k = r % 128;
        const float* W = which == 0 ? Wk : (which == 1 ? Wq : Wv);
        __half* D = which == 0 ? g_Wkt : (which == 1 ? g_Wqt : g_Wvt);
        D[r] = __float2half_rn(W[(size_t)(c >> 5) * (HID * AD) + (size_t)k * AD + (c & 31)]);
    } else {
        int j = iw - nWe - nWs - 3 * nH;
        int n = j / (128 * 256), r = j % (128 * 256);
        int c = r / 256, k = r % 256;
        g_Wc1t[j] = __float2half_rn(Wc1[((size_t)n * 256 + k) * 128 + c]);
    }
}

// ---------------- common GEMM core: 4-stage cp.async, 128x128, 8 warps -------------
__device__ __forceinline__ void gemm_core(
    const __half* A1n, int a1w, const __half* A2n, int a2w,
    const __half* Wtn, int Ktot,
    const float* bn, int dorelu, __half* Cn,
    unsigned (*As)[128 * SROW], unsigned (*Bs)[128 * SROW], int b0g)
{
    int tid = threadIdx.x;
    int wid = tid >> 5, lane = tid & 31;
    int grp = lane >> 2, tig = lane & 3;
    int wm  = (wid >> 2) * 64;
    int wn  = (wid & 3) * 32;
    int am  = tid >> 1, ahs = tid & 1;

    uint32_t sA = (uint32_t)__cvta_generic_to_shared(&As[0][0]);
    uint32_t sB = (uint32_t)__cvta_generic_to_shared(&Bs[0][0]);
    uint32_t sOff = (am * SROW + ahs * 4) * 4;
    const __half* bRow = Wtn + (size_t)am * Ktot;

    auto fill = [&](int kt) {
        int s  = kt % GSTG;
        int k  = kt * 16 + ahs * 8;
        const __half* asrc;
        if (k < a1w) asrc = A1n + (size_t)(b0g + am) * a1w + k;
        else         asrc = A2n + (size_t)(b0g + am) * a2w + (k - a1w);
        CPA16(sA + s * (128 * SROW * 4) + sOff, asrc);
        CPA16(sB + s * (128 * SROW * 4) + sOff, bRow + k);
        CP_COMMIT();
    };

    float acc[4][4][4];
    #pragma unroll
    for (int mt = 0; mt < 4; mt++)
        #pragma unroll
        for (int nt = 0; nt < 4; nt++)
            #pragma unroll
            for (int r = 0; r < 4; r++) acc[mt][nt][r] = 0.f;

    int nkt = Ktot >> 4;
    fill(0); fill(1); fill(2);

    for (int kt = 0; kt < nkt; kt++) {
        int rem = nkt - 1 - kt;
        if (rem >= 2)      { CP_WAIT2(); }
        else if (rem == 1) { CP_WAIT1(); }
        else               { CP_WAIT0(); }
        __syncthreads();
        const unsigned* Ab = As[kt % GSTG];
        const unsigned* Bb = Bs[kt % GSTG];
        unsigned af[4][4];
        #pragma unroll
        for (int mt = 0; mt < 4; mt++) {
            int m = wm + mt * 16 + grp;
            af[mt][0] = Ab[m * SROW + tig];
            af[mt][1] = Ab[(m + 8) * SROW + tig];
            af[mt][2] = Ab[m * SROW + tig + 4];
            af[mt][3] = Ab[(m + 8) * SROW + tig + 4];
        }
        unsigned bf[4][2];
        #pragma unroll
        for (int nt = 0; nt < 4; nt++) {
            int c = wn + nt * 8 + grp;
            bf[nt][0] = Bb[c * SROW + tig];
            bf[nt][1] = Bb[c * SROW + tig + 4];
        }
        #pragma unroll
        for (int mt = 0; mt < 4; mt++)
            #pragma unroll
            for (int nt = 0; nt < 4; nt++)
                MMA16(acc[mt][nt], af[mt][0], af[mt][1], af[mt][2], af[mt][3],
                      bf[nt][0], bf[nt][1]);
        if (kt + 3 < nkt) fill(kt + 3);
    }

    #pragma unroll
    for (int nt = 0; nt < 4; nt++) {
        int col = wn + nt * 8 + tig * 2;
        float bj0 = bn ? bn[col]     : 0.f;
        float bj1 = bn ? bn[col + 1] : 0.f;
        #pragma unroll
        for (int mt = 0; mt < 4; mt++) {
            int row0 = b0g + wm + mt * 16 + grp;
            float v0 = acc[mt][nt][0] + bj0;
            float v1 = acc[mt][nt][1] + bj1;
            float v2 = acc[mt][nt][2] + bj0;
            float v3 = acc[mt][nt][3] + bj1;
            if (dorelu) {
                v0 = fmaxf(v0, 0.f); v1 = fmaxf(v1, 0.f);
                v2 = fmaxf(v2, 0.f); v3 = fmaxf(v3, 0.f);
            }
            *(__half2*)&Cn[(size_t)row0 * 128 + col]       = __floats2half2_rn(v0, v1);
            *(__half2*)&Cn[(size_t)(row0 + 8) * 128 + col] = __floats2half2_rn(v2, v3);
        }
    }
}

// ---------------- merged encoder launch: y=0 -> sa_enc (K=144), y=1 -> s_enc -------
__global__ void __launch_bounds__(256, 3)
enc_kernel(const float* __restrict__ be, const float* __restrict__ bs)
{
    __shared__ __align__(16) unsigned As[GSTG][128 * SROW];
    __shared__ __align__(16) unsigned Bs[GSTG][128 * SROW];
    int n = blockIdx.z, b0g = blockIdx.x * 128;
    const __half* sthn = g_sth + (size_t)n * BATCH * SDIM;
    if (blockIdx.y == 0) {
        gemm_core(sthn, SDIM, g_ach + (size_t)n * BATCH * ADIM, ADIM,
                  g_Wet + (size_t)n * 128 * 144, 144,
                  be + n * 128, 1, g_sa + (size_t)n * BATCH * 128, As, Bs, b0g);
    } else {
        gemm_core(sthn, SDIM, sthn, SDIM,
                  g_Wst + (size_t)n * 128 * 128, 128,
                  bs + n * 128, 1, g_se + (size_t)n * BATCH * 128, As, Bs, b0g);
    }
}

// ---------------- merged K/Q/V launch: y=0 K, y=1 Q, y=2 V --------------------------
__global__ void __launch_bounds__(256, 3)
kqv_kernel(const float* __restrict__ bv)
{
    __shared__ __align__(16) unsigned As[GSTG][128 * SROW];
    __shared__ __align__(16) unsigned Bs[GSTG][128 * SROW];
    int n = blockIdx.z, b0g = blockIdx.x * 128;
    const __half* san = g_sa + (size_t)n * BATCH * 128;
    const __half* sen = g_se + (size_t)n * BATCH * 128;
    if (blockIdx.y == 0) {
        gemm_core(san, HID, san, HID, g_Wkt, 128,
                  nullptr, 0, g_Kb + (size_t)n * BATCH * 128, As, Bs, b0g);
    } else if (blockIdx.y == 1) {
        gemm_core(sen, HID, sen, HID, g_Wqt, 128,
                  nullptr, 0, g_Qb + (size_t)n * BATCH * 128, As, Bs, b0g);
    } else {
        gemm_core(san, HID, san, HID, g_Wvt, 128,
                  bv, 1, g_Vb + (size_t)n * BATCH * 128, As, Bs, b0g);
    }
}

// ---------------- pipelined fused critic (3 stages) --------------------------------
__global__ void __launch_bounds__(256, 3)
critic16p(const float* __restrict__ actions,
          const float* __restrict__ bc1, const float* __restrict__ Wc2,
          const float* __restrict__ bc2, float* __restrict__ out)
{
    __shared__ __align__(16) unsigned As[CSTG][128 * SROW];
    __shared__ __align__(16) unsigned Bs[CSTG][128 * SROW];
    __shared__ float Wc2s[128 * 16];
    __shared__ float bc1s[128];
    __shared__ float bc2s[16];
    __shared__ float rowacc[128];
    __shared__ int   amaxs[128];

    int n   = blockIdx.z;
    int b0g = blockIdx.x * 128;
    int tid = threadIdx.x;
    int wid = tid >> 5, lane = tid & 31;
    int grp = lane >> 2, tig = lane & 3;
    int wm  = (wid >> 2) * 64;
    int wn  = (wid & 3) * 32;
    int am  = tid >> 1, ahs = tid & 1;

    const __half* A1n = g_se  + (size_t)n * BATCH * 128;
    const __half* A2n = g_oth + (size_t)n * BATCH * 128;
    const __half* Wtn = g_Wc1t + (size_t)n * 128 * 256;
    const float*  Wc2n = Wc2 + (size_t)n * 128 * 16;

    #pragma unroll
    for (int t = 0; t < 2; t++) {
        int f = tid + t * 256;
        *(float4*)&Wc2s[f * 4] = *(const float4*)&Wc2n[f * 4];
    }
    if (tid < 128) {
        bc1s[tid] = bc1[n * 128 + tid];
        rowacc[tid] = 0.f;
        const float* ap = actions + ((size_t)n * BATCH + b0g + tid) * 16;
        float best = ap[0]; int bi = 0;
        #pragma unroll
        for (int c = 1; c < 16; c++) { float v = ap[c]; if (v > best) { best = v; bi = c; } }
        amaxs[tid] = bi;
    }
    if (tid < 16) bc2s[tid] = bc2[n * 16 + tid];

    uint32_t sA = (uint32_t)__cvta_generic_to_shared(&As[0][0]);
    uint32_t sB = (uint32_t)__cvta_generic_to_shared(&Bs[0][0]);
    uint32_t sOff = (am * SROW + ahs * 4) * 4;
    const __half* bRow = Wtn + (size_t)am * 256;

    auto fill = [&](int kt) {
        int s = kt % CSTG;
        int k = kt * 16 + ahs * 8;
        const __half* asrc = (k < 128) ? (A1n + (size_t)(b0g + am) * 128 + k)
                                       : (A2n + (size_t)(b0g + am) * 128 + (k - 128));
        CPA16(sA + s * (128 * SROW * 4) + sOff, asrc);
        CPA16(sB + s * (128 * SROW * 4) + sOff, bRow + k);
        CP_COMMIT();
    };

    float acc[4][4][4];
    #pragma unroll
    for (int mt = 0; mt < 4; mt++)
        #pragma unroll
        for (int nt = 0; nt < 4; nt++)
            #pragma unroll
            for (int r = 0; r < 4; r++) acc[mt][nt][r] = 0.f;

    const int nkt = 16;
    fill(0);
    fill(1);

    for (int kt = 0; kt < nkt; kt++) {
        if (kt + 1 < nkt) { CP_WAIT1(); } else { CP_WAIT0(); }
        __syncthreads();
        const unsigned* Ab = As[kt % CSTG];
        const unsigned* Bb = Bs[kt % CSTG];
        unsigned af[4][4];
        #pragma unroll
        for (int mt = 0; mt < 4; mt++) {
            int m = wm + mt * 16 + grp;
            af[mt][0] = Ab[m * SROW + tig];
            af[mt][1] = Ab[(m + 8) * SROW + tig];
            af[mt][2] = Ab[m * SROW + tig + 4];
            af[mt][3] = Ab[(m + 8) * SROW + tig + 4];
        }
        unsigned bf[4][2];
        #pragma unroll
        for (int nt = 0; nt < 4; nt++) {
            int c = wn + nt * 8 + grp;
            bf[nt][0] = Bb[c * SROW + tig];
            bf[nt][1] = Bb[c * SROW + tig + 4];
        }
        #pragma unroll
        for (int mt = 0; mt < 4; mt++)
            #pragma unroll
            for (int nt = 0; nt < 4; nt++)
                MMA16(acc[mt][nt], af[mt][0], af[mt][1], af[mt][2], af[mt][3],
                      bf[nt][0], bf[nt][1]);
        if (kt + 2 < nkt) fill(kt + 2);
    }

    #pragma unroll
    for (int mt = 0; mt < 4; mt++) {
        int row0 = wm + mt * 16 + grp;
        int a0 = amaxs[row0];
        int a1 = amaxs[row0 + 8];
        float p0 = 0.f, p1 = 0.f;
        #pragma unroll
        for (int nt = 0; nt < 4; nt++) {
            int col = wn + nt * 8 + tig * 2;
            float bj0 = bc1s[col], bj1 = bc1s[col + 1];
            float h00 = fmaxf(acc[mt][nt][0] + bj0, 0.f);
            float h01 = fmaxf(acc[mt][nt][1] + bj1, 0.f);
            float h10 = fmaxf(acc[mt][nt][2] + bj0, 0.f);
            float h11 = fmaxf(acc[mt][nt][3] + bj1, 0.f);
            p0 += h00 * Wc2s[col * 16 + a0] + h01 * Wc2s[(col + 1) * 16 + a0];
            p1 += h10 * Wc2s[col * 16 + a1] + h11 * Wc2s[(col + 1) * 16 + a1];
        }
        p0 += __shfl_xor_sync(0xffffffffu, p0, 1);
        p0 += __shfl_xor_sync(0xffffffffu, p0, 2);
        p1 += __shfl_xor_sync(0xffffffffu, p1, 1);
        p1 += __shfl_xor_sync(0xffffffffu, p1, 2);
        if (tig == 0) {
            atomicAdd(&rowacc[row0], p0);
            atomicAdd(&rowacc[row0 + 8], p1);
        }
    }
    __syncthreads();
    if (tid < 128)
        out[(size_t)n * BATCH + b0g + tid] = rowacc[tid] + bc2s[amaxs[tid]];
}

// ---------------- attention (unchanged) --------------------------------------------
__global__ void __launch_bounds__(256)
attn_kernel()
{
    __shared__ float Ks[4 * 8 * 128];
    __shared__ float Vs[4 * 8 * 128];
    int tid = threadIdx.x;
    int b0  = blockIdx.x * 4;

    #pragma unroll
    for (int t = 0; t < 2; t++) {
        int f  = tid + t * 256;
        int c8 = f & 15;
        int rj = f >> 4;
        int r  = rj & 3, j = rj >> 2;
        size_t g = ((size_t)j * BATCH + b0 + r) * 128 + c8 * 8;
        int s = (r * 8 + j) * 128 + c8 * 8;
        uint4 uk = *(const uint4*)(g_Kb + g);
        uint4 uv = *(const uint4*)(g_Vb + g);
        const __half2* hk = (const __half2*)&uk;
        const __half2* hv = (const __half2*)&uv;
        #pragma unroll
        for (int p = 0; p < 4; p++) {
            float2 fk = __half22float2(hk[p]);
            float2 fv = __half22float2(hv[p]);
            Ks[s + p * 2]     = fk.x;
            Ks[s + p * 2 + 1] = fk.y;
            Vs[s + p * 2]     = fv.x;
            Vs[s + p * 2 + 1] = fv.y;
        }
    }
    __syncthreads();

    int hf = tid & 1;
    int i  = (tid >> 1) & 7;
    int k  = (tid >> 4) & 3;
    int r  = tid >> 6;

    float q[16];
    size_t base = ((size_t)i * BATCH + b0 + r) * 128 + k * 32 + hf * 16;
    {
        uint4 u0 = *(const uint4*)(g_Qb + base);
        uint4 u1 = *(const uint4*)(g_Qb + base + 8);
        const __half2* h0 = (const __half2*)&u0;
        const __half2* h1 = (const __half2*)&u1;
        #pragma unroll
        for (int p = 0; p < 4; p++) {
            float2 f0 = __half22float2(h0[p]);
            float2 f1 = __half22float2(h1[p]);
            q[p * 2] = f0.x; q[p * 2 + 1] = f0.y;
            q[8 + p * 2] = f1.x; q[8 + p * 2 + 1] = f1.y;
        }
    }

    float lg[8];
    #pragma unroll
    for (int j = 0; j < 8; j++) {
        const float* kp = &Ks[(r * 8 + j) * 128 + k * 32 + hf * 16];
        float d = 0.f;
        #pragma unroll
        for (int dd = 0; dd < 16; dd++) d += q[dd] * kp[dd];
        d += __shfl_xor_sync(0xffffffffu, d, 1);
        lg[j] = (j == i) ? -1e9f : d * 0.17677669529663687f;
    }
    float m = lg[0];
    #pragma unroll
    for (int j = 1; j < 8; j++) m = fmaxf(m, lg[j]);
    float ssum = 0.f;
    #pragma unroll
    for (int j = 0; j < 8; j++) { lg[j] = __expf(lg[j] - m); ssum += lg[j]; }
    float inv = 1.f / ssum;

    float acc[16];
    #pragma unroll
    for (int dd = 0; dd < 16; dd++) acc[dd] = 0.f;
    #pragma unroll
    for (int j = 0; j < 8; j++) {
        float p = lg[j] * inv;
        const float* vp = &Vs[(r * 8 + j) * 128 + k * 32 + hf * 16];
        #pragma unroll
        for (int dd = 0; dd < 16; dd++) acc[dd] += p * vp[dd];
    }
    {
        uint4 u0, u1;
        unsigned* w0 = (unsigned*)&u0;
        unsigned* w1 = (unsigned*)&u1;
        #pragma unroll
        for (int p = 0; p < 4; p++) {
            w0[p] = pkh2(acc[p * 2], acc[p * 2 + 1]);
            w1[p] = pkh2(acc[8 + p * 2], acc[8 + p * 2 + 1]);
        }
        *(uint4*)(g_oth + base)     = u0;
        *(uint4*)(g_oth + base + 8) = u1;
    }
}

// ---------------- launch -----------------------------------------------------------
extern "C" void kernel_launch(void* const* d_in, const int* in_sizes, int n_in,
                              void* d_out, int out_size)
{
    const float* states  = (const float*)d_in[0];
    const float* actions = (const float*)d_in[1];
    const float* We      = (const float*)d_in[2];
    const float* be      = (const float*)d_in[3];
    const float* Wse     = (const float*)d_in[4];
    const float* bs      = (const float*)d_in[5];
    const float* Wk      = (const float*)d_in[6];
    const float* Wq      = (const float*)d_in[7];
    const float* Wv      = (const float*)d_in[8];
    const float* bv      = (const float*)d_in[9];
    const float* Wc1     = (const float*)d_in[10];
    const float* bc1     = (const float*)d_in[11];
    const float* Wc2     = (const float*)d_in[12];
    const float* bc2     = (const float*)d_in[13];
    float* out = (float*)d_out;

    size_t ncvt = (size_t)NAG * BATCH * (SDIM + ADIM) / 8;
    size_t nw   = (size_t)NAG * 128 * 144 + NAG * 128 * 128 + 3 * 128 * 128
                + (size_t)NAG * 128 * 256;
    size_t ntot = ncvt + nw;
    prep_all<<<(unsigned)((ntot + 255) / 256), 256>>>(states, actions, We, Wse,
                                                      Wk, Wq, Wv, Wc1);

    enc_kernel<<<dim3(BATCH / 128, 2, NAG), 256>>>(be, bs);
    kqv_kernel<<<dim3(BATCH / 128, 3, NAG), 256>>>(bv);
    attn_kernel<<<BATCH / 4, 256>>>();
    critic16p<<<dim3(BATCH / 128, 1, NAG), 256>>>(actions, bc1, Wc2, bc2, out);
}

// round 14
// speedup vs baseline: 1.3657x; 1.3657x over previous
#include <cuda_runtime.h>
#include <cuda_fp16.h>
#include <cstdint>

#define NAG   8
#define BATCH 32768
#define SDIM  128
#define ADIM  16
#define HID   128
#define HEADS 4
#define AD    32

// ---------------- scratch (device globals; no allocation allowed) ----------------
__device__ __half g_sa [(size_t)NAG * BATCH * HID];
__device__ __half g_se [(size_t)NAG * BATCH * HID];
__device__ __half g_Kb [(size_t)NAG * BATCH * HID];
__device__ __half g_Qb [(size_t)NAG * BATCH * HID];
__device__ __half g_Vb [(size_t)NAG * BATCH * HID];
__device__ __half g_oth[(size_t)NAG * BATCH * HID];
__device__ __half g_sth[(size_t)NAG * BATCH * SDIM];
__device__ __half g_ach[(size_t)NAG * BATCH * ADIM];
__device__ __half g_Wet [NAG * 128 * 144];
__device__ __half g_Wst [NAG * 128 * 128];
__device__ __half g_Wkt [128 * 128];
__device__ __half g_Wqt [128 * 128];
__device__ __half g_Wvt [128 * 128];
__device__ __half g_Wc1t[NAG * 128 * 256];

__device__ __forceinline__ unsigned pkh2(float a, float b) {
    __half2 h = __floats2half2_rn(a, b);
    return *(unsigned*)&h;
}

#define SROW 12          // 8 data words (16 halves) + 4 pad; frag banks bijective
#define GSTG 4           // GEMM pipeline stages (prefetch distance 3)
#define CSTG 3           // critic pipeline stages

#define MMA16(acc, a0, a1, a2, a3, b0, b1)                                        \
    asm("mma.sync.aligned.m16n8k16.row.col.f32.f16.f16.f32 "                      \
        "{%0,%1,%2,%3}, {%4,%5,%6,%7}, {%8,%9}, {%0,%1,%2,%3};"                   \
        : "+f"((acc)[0]), "+f"((acc)[1]), "+f"((acc)[2]), "+f"((acc)[3])          \
        : "r"(a0), "r"(a1), "r"(a2), "r"(a3), "r"(b0), "r"(b1))

#define CPA16(dst, src) \
    asm volatile("cp.async.cg.shared.global [%0], [%1], 16;\n" :: "r"(dst), "l"(src))
#define CP_COMMIT()  asm volatile("cp.async.commit_group;\n")
#define CP_WAIT2()   asm volatile("cp.async.wait_group 2;\n")
#define CP_WAIT1()   asm volatile("cp.async.wait_group 1;\n")
#define CP_WAIT0()   asm volatile("cp.async.wait_group 0;\n")

// ---------------- merged prep: input fp16 copies + transposed fp16 weights ---------
__global__ void prep_all(const float* __restrict__ states,
                         const float* __restrict__ actions,
                         const float* __restrict__ We, const float* __restrict__ Ws,
                         const float* __restrict__ Wk, const float* __restrict__ Wq,
                         const float* __restrict__ Wv, const float* __restrict__ Wc1)
{
    size_t i  = (size_t)blockIdx.x * blockDim.x + threadIdx.x;
    size_t ns = (size_t)NAG * BATCH * SDIM / 8;
    size_t na = (size_t)NAG * BATCH * ADIM / 8;
    if (i < ns) {
        const float4* s = (const float4*)states + i * 2;
        float4 a = s[0], b = s[1];
        uint4 u = { pkh2(a.x, a.y), pkh2(a.z, a.w), pkh2(b.x, b.y), pkh2(b.z, b.w) };
        *(uint4*)(g_sth + i * 8) = u;
        return;
    }
    if (i < ns + na) {
        size_t j = i - ns;
        const float4* s = (const float4*)actions + j * 2;
        float4 a = s[0], b = s[1];
        uint4 u = { pkh2(a.x, a.y), pkh2(a.z, a.w), pkh2(b.x, b.y), pkh2(b.z, b.w) };
        *(uint4*)(g_ach + j * 8) = u;
        return;
    }
    long w = (long)(i - ns - na);
    const int nWe = NAG * 128 * 144;
    const int nWs = NAG * 128 * 128;
    const int nH  = 128 * 128;
    const int nWc = NAG * 128 * 256;
    if (w < 0 || w >= nWe + nWs + 3 * nH + nWc) return;
    int iw = (int)w;
    if (iw < nWe) {
        int n = iw / (128 * 144), r = iw % (128 * 144);
        int c = r / 144, k = r % 144;
        g_Wet[iw] = __float2half_rn(We[((size_t)n * 144 + k) * 128 + c]);
    } else if (iw < nWe + nWs) {
        int j = iw - nWe;
        int n = j / (128 * 128), r = j % (128 * 128);
        int c = r / 128, k = r % 128;
        g_Wst[j] = __float2half_rn(Ws[((size_t)n * 128 + k) * 128 + c]);
    } else if (iw < nWe + nWs + 3 * nH) {
        int j = iw - nWe - nWs;
        int which = j / nH, r = j % nH;
        int c = r / 128, k = r % 128;
        const float* W = which == 0 ? Wk : (which == 1 ? Wq : Wv);
        __half* D = which == 0 ? g_Wkt : (which == 1 ? g_Wqt : g_Wvt);
        D[r] = __float2half_rn(W[(size_t)(c >> 5) * (HID * AD) + (size_t)k * AD + (c & 31)]);
    } else {
        int j = iw - nWe - nWs - 3 * nH;
        int n = j / (128 * 256), r = j % (128 * 256);
        int c = r / 256, k = r % 256;
        g_Wc1t[j] = __float2half_rn(Wc1[((size_t)n * 256 + k) * 128 + c]);
    }
}

// ---------------- common GEMM core: 4-stage cp.async, 128x128, 8 warps -------------
__device__ __forceinline__ void gemm_core(
    const __half* A1n, int a1w, const __half* A2n, int a2w,
    const __half* Wtn, int Ktot,
    const float* bn, int dorelu, __half* Cn,
    unsigned (*As)[128 * SROW], unsigned (*Bs)[128 * SROW], int b0g)
{
    int tid = threadIdx.x;
    int wid = tid >> 5, lane = tid & 31;
    int grp = lane >> 2, tig = lane & 3;
    int wm  = (wid >> 2) * 64;
    int wn  = (wid & 3) * 32;
    int am  = tid >> 1, ahs = tid & 1;

    uint32_t sA = (uint32_t)__cvta_generic_to_shared(&As[0][0]);
    uint32_t sB = (uint32_t)__cvta_generic_to_shared(&Bs[0][0]);
    uint32_t sOff = (am * SROW + ahs * 4) * 4;
    const __half* bRow = Wtn + (size_t)am * Ktot;

    auto fill = [&](int kt) {
        int s  = kt % GSTG;
        int k  = kt * 16 + ahs * 8;
        const __half* asrc;
        if (k < a1w) asrc = A1n + (size_t)(b0g + am) * a1w + k;
        else         asrc = A2n + (size_t)(b0g + am) * a2w + (k - a1w);
        CPA16(sA + s * (128 * SROW * 4) + sOff, asrc);
        CPA16(sB + s * (128 * SROW * 4) + sOff, bRow + k);
        CP_COMMIT();
    };

    float acc[4][4][4];
    #pragma unroll
    for (int mt = 0; mt < 4; mt++)
        #pragma unroll
        for (int nt = 0; nt < 4; nt++)
            #pragma unroll
            for (int r = 0; r < 4; r++) acc[mt][nt][r] = 0.f;

    int nkt = Ktot >> 4;
    fill(0); fill(1); fill(2);

    for (int kt = 0; kt < nkt; kt++) {
        int rem = nkt - 1 - kt;
        if (rem >= 2)      { CP_WAIT2(); }
        else if (rem == 1) { CP_WAIT1(); }
        else               { CP_WAIT0(); }
        __syncthreads();
        const unsigned* Ab = As[kt % GSTG];
        const unsigned* Bb = Bs[kt % GSTG];
        unsigned af[4][4];
        #pragma unroll
        for (int mt = 0; mt < 4; mt++) {
            int m = wm + mt * 16 + grp;
            af[mt][0] = Ab[m * SROW + tig];
            af[mt][1] = Ab[(m + 8) * SROW + tig];
            af[mt][2] = Ab[m * SROW + tig + 4];
            af[mt][3] = Ab[(m + 8) * SROW + tig + 4];
        }
        unsigned bf[4][2];
        #pragma unroll
        for (int nt = 0; nt < 4; nt++) {
            int c = wn + nt * 8 + grp;
            bf[nt][0] = Bb[c * SROW + tig];
            bf[nt][1] = Bb[c * SROW + tig + 4];
        }
        #pragma unroll
        for (int mt = 0; mt < 4; mt++)
            #pragma unroll
            for (int nt = 0; nt < 4; nt++)
                MMA16(acc[mt][nt], af[mt][0], af[mt][1], af[mt][2], af[mt][3],
                      bf[nt][0], bf[nt][1]);
        if (kt + 3 < nkt) fill(kt + 3);
    }

    #pragma unroll
    for (int nt = 0; nt < 4; nt++) {
        int col = wn + nt * 8 + tig * 2;
        float bj0 = bn ? bn[col]     : 0.f;
        float bj1 = bn ? bn[col + 1] : 0.f;
        #pragma unroll
        for (int mt = 0; mt < 4; mt++) {
            int row0 = b0g + wm + mt * 16 + grp;
            float v0 = acc[mt][nt][0] + bj0;
            float v1 = acc[mt][nt][1] + bj1;
            float v2 = acc[mt][nt][2] + bj0;
            float v3 = acc[mt][nt][3] + bj1;
            if (dorelu) {
                v0 = fmaxf(v0, 0.f); v1 = fmaxf(v1, 0.f);
                v2 = fmaxf(v2, 0.f); v3 = fmaxf(v3, 0.f);
            }
            *(__half2*)&Cn[(size_t)row0 * 128 + col]       = __floats2half2_rn(v0, v1);
            *(__half2*)&Cn[(size_t)(row0 + 8) * 128 + col] = __floats2half2_rn(v2, v3);
        }
    }
}

// ---------------- merged encoder launch: y=0 -> sa_enc (K=144), y=1 -> s_enc -------
__global__ void __launch_bounds__(256)
enc_kernel(const float* __restrict__ be, const float* __restrict__ bs)
{
    __shared__ __align__(16) unsigned As[GSTG][128 * SROW];
    __shared__ __align__(16) unsigned Bs[GSTG][128 * SROW];
    int n = blockIdx.z, b0g = blockIdx.x * 128;
    const __half* sthn = g_sth + (size_t)n * BATCH * SDIM;
    if (blockIdx.y == 0) {
        gemm_core(sthn, SDIM, g_ach + (size_t)n * BATCH * ADIM, ADIM,
                  g_Wet + (size_t)n * 128 * 144, 144,
                  be + n * 128, 1, g_sa + (size_t)n * BATCH * 128, As, Bs, b0g);
    } else {
        gemm_core(sthn, SDIM, sthn, SDIM,
                  g_Wst + (size_t)n * 128 * 128, 128,
                  bs + n * 128, 1, g_se + (size_t)n * BATCH * 128, As, Bs, b0g);
    }
}

// ---------------- merged K/Q/V launch: y=0 K, y=1 Q, y=2 V --------------------------
__global__ void __launch_bounds__(256)
kqv_kernel(const float* __restrict__ bv)
{
    __shared__ __align__(16) unsigned As[GSTG][128 * SROW];
    __shared__ __align__(16) unsigned Bs[GSTG][128 * SROW];
    int n = blockIdx.z, b0g = blockIdx.x * 128;
    const __half* san = g_sa + (size_t)n * BATCH * 128;
    const __half* sen = g_se + (size_t)n * BATCH * 128;
    if (blockIdx.y == 0) {
        gemm_core(san, HID, san, HID, g_Wkt, 128,
                  nullptr, 0, g_Kb + (size_t)n * BATCH * 128, As, Bs, b0g);
    } else if (blockIdx.y == 1) {
        gemm_core(sen, HID, sen, HID, g_Wqt, 128,
                  nullptr, 0, g_Qb + (size_t)n * BATCH * 128, As, Bs, b0g);
    } else {
        gemm_core(san, HID, san, HID, g_Wvt, 128,
                  bv, 1, g_Vb + (size_t)n * BATCH * 128, As, Bs, b0g);
    }
}

// ---------------- pipelined fused critic (3 stages; R12 proven) --------------------
__global__ void __launch_bounds__(256)
critic16p(const float* __restrict__ actions,
          const float* __restrict__ bc1, const float* __restrict__ Wc2,
          const float* __restrict__ bc2, float* __restrict__ out)
{
    __shared__ __align__(16) unsigned As[CSTG][128 * SROW];
    __shared__ __align__(16) unsigned Bs[CSTG][128 * SROW];
    __shared__ float Wc2s[128 * 16];
    __shared__ float bc1s[128];
    __shared__ float bc2s[16];
    __shared__ float rowacc[128];
    __shared__ int   amaxs[128];

    int n   = blockIdx.z;
    int b0g = blockIdx.x * 128;
    int tid = threadIdx.x;
    int wid = tid >> 5, lane = tid & 31;
    int grp = lane >> 2, tig = lane & 3;
    int wm  = (wid >> 2) * 64;
    int wn  = (wid & 3) * 32;
    int am  = tid >> 1, ahs = tid & 1;

    const __half* A1n = g_se  + (size_t)n * BATCH * 128;
    const __half* A2n = g_oth + (size_t)n * BATCH * 128;
    const __half* Wtn = g_Wc1t + (size_t)n * 128 * 256;
    const float*  Wc2n = Wc2 + (size_t)n * 128 * 16;

    #pragma unroll
    for (int t = 0; t < 2; t++) {
        int f = tid + t * 256;
        *(float4*)&Wc2s[f * 4] = *(const float4*)&Wc2n[f * 4];
    }
    if (tid < 128) {
        bc1s[tid] = bc1[n * 128 + tid];
        rowacc[tid] = 0.f;
        const float* ap = actions + ((size_t)n * BATCH + b0g + tid) * 16;
        float best = ap[0]; int bi = 0;
        #pragma unroll
        for (int c = 1; c < 16; c++) { float v = ap[c]; if (v > best) { best = v; bi = c; } }
        amaxs[tid] = bi;
    }
    if (tid < 16) bc2s[tid] = bc2[n * 16 + tid];

    uint32_t sA = (uint32_t)__cvta_generic_to_shared(&As[0][0]);
    uint32_t sB = (uint32_t)__cvta_generic_to_shared(&Bs[0][0]);
    uint32_t sOff = (am * SROW + ahs * 4) * 4;
    const __half* bRow = Wtn + (size_t)am * 256;

    auto fill = [&](int kt) {
        int s = kt % CSTG;
        int k = kt * 16 + ahs * 8;
        const __half* asrc = (k < 128) ? (A1n + (size_t)(b0g + am) * 128 + k)
                                       : (A2n + (size_t)(b0g + am) * 128 + (k - 128));
        CPA16(sA + s * (128 * SROW * 4) + sOff, asrc);
        CPA16(sB + s * (128 * SROW * 4) + sOff, bRow + k);
        CP_COMMIT();
    };

    float acc[4][4][4];
    #pragma unroll
    for (int mt = 0; mt < 4; mt++)
        #pragma unroll
        for (int nt = 0; nt < 4; nt++)
            #pragma unroll
            for (int r = 0; r < 4; r++) acc[mt][nt][r] = 0.f;

    const int nkt = 16;
    fill(0);
    fill(1);

    for (int kt = 0; kt < nkt; kt++) {
        if (kt + 1 < nkt) { CP_WAIT1(); } else { CP_WAIT0(); }
        __syncthreads();
        const unsigned* Ab = As[kt % CSTG];
        const unsigned* Bb = Bs[kt % CSTG];
        unsigned af[4][4];
        #pragma unroll
        for (int mt = 0; mt < 4; mt++) {
            int m = wm + mt * 16 + grp;
            af[mt][0] = Ab[m * SROW + tig];
            af[mt][1] = Ab[(m + 8) * SROW + tig];
            af[mt][2] = Ab[m * SROW + tig + 4];
            af[mt][3] = Ab[(m + 8) * SROW + tig + 4];
        }
        unsigned bf[4][2];
        #pragma unroll
        for (int nt = 0; nt < 4; nt++) {
            int c = wn + nt * 8 + grp;
            bf[nt][0] = Bb[c * SROW + tig];
            bf[nt][1] = Bb[c * SROW + tig + 4];
        }
        #pragma unroll
        for (int mt = 0; mt < 4; mt++)
            #pragma unroll
            for (int nt = 0; nt < 4; nt++)
                MMA16(acc[mt][nt], af[mt][0], af[mt][1], af[mt][2], af[mt][3],
                      bf[nt][0], bf[nt][1]);
        if (kt + 2 < nkt) fill(kt + 2);
    }

    #pragma unroll
    for (int mt = 0; mt < 4; mt++) {
        int row0 = wm + mt * 16 + grp;
        int a0 = amaxs[row0];
        int a1 = amaxs[row0 + 8];
        float p0 = 0.f, p1 = 0.f;
        #pragma unroll
        for (int nt = 0; nt < 4; nt++) {
            int col = wn + nt * 8 + tig * 2;
            float bj0 = bc1s[col], bj1 = bc1s[col + 1];
            float h00 = fmaxf(acc[mt][nt][0] + bj0, 0.f);
            float h01 = fmaxf(acc[mt][nt][1] + bj1, 0.f);
            float h10 = fmaxf(acc[mt][nt][2] + bj0, 0.f);
            float h11 = fmaxf(acc[mt][nt][3] + bj1, 0.f);
            p0 += h00 * Wc2s[col * 16 + a0] + h01 * Wc2s[(col + 1) * 16 + a0];
            p1 += h10 * Wc2s[col * 16 + a1] + h11 * Wc2s[(col + 1) * 16 + a1];
        }
        p0 += __shfl_xor_sync(0xffffffffu, p0, 1);
        p0 += __shfl_xor_sync(0xffffffffu, p0, 2);
        p1 += __shfl_xor_sync(0xffffffffu, p1, 1);
        p1 += __shfl_xor_sync(0xffffffffu, p1, 2);
        if (tig == 0) {
            atomicAdd(&rowacc[row0], p0);
            atomicAdd(&rowacc[row0 + 8], p1);
        }
    }
    __syncthreads();
    if (tid < 128)
        out[(size_t)n * BATCH + b0g + tid] = rowacc[tid] + bc2s[amaxs[tid]];
}

// ---------------- attention: fp16 smem staging, fp32 math --------------------------
__global__ void __launch_bounds__(256)
attn_kernel()
{
    __shared__ __align__(16) __half Ks[4 * 8 * 128];   // 8 KB
    __shared__ __align__(16) __half Vs[4 * 8 * 128];   // 8 KB
    int tid = threadIdx.x;
    int b0  = blockIdx.x * 4;

    // stage raw fp16: 512 uint4 per array, 256 threads x 2
    #pragma unroll
    for (int t = 0; t < 2; t++) {
        int f  = tid + t * 256;
        int c8 = f & 15;
        int rj = f >> 4;
        int r  = rj & 3, j = rj >> 2;
        size_t g = ((size_t)j * BATCH + b0 + r) * 128 + c8 * 8;
        int s = (r * 8 + j) * 128 + c8 * 8;
        *(uint4*)(Ks + s) = *(const uint4*)(g_Kb + g);
        *(uint4*)(Vs + s) = *(const uint4*)(g_Vb + g);
    }
    __syncthreads();

    int hf = tid & 1;
    int i  = (tid >> 1) & 7;
    int k  = (tid >> 4) & 3;
    int r  = tid >> 6;

    float q[16];
    size_t base = ((size_t)i * BATCH + b0 + r) * 128 + k * 32 + hf * 16;
    {
        uint4 u0 = *(const uint4*)(g_Qb + base);
        uint4 u1 = *(const uint4*)(g_Qb + base + 8);
        const __half2* h0 = (const __half2*)&u0;
        const __half2* h1 = (const __half2*)&u1;
        #pragma unroll
        for (int p = 0; p < 4; p++) {
            float2 f0 = __half22float2(h0[p]);
            float2 f1 = __half22float2(h1[p]);
            q[p * 2] = f0.x; q[p * 2 + 1] = f0.y;
            q[8 + p * 2] = f1.x; q[8 + p * 2 + 1] = f1.y;
        }
    }

    int soff = k * 32 + hf * 16;
    float lg[8];
    #pragma unroll
    for (int j = 0; j < 8; j++) {
        const __half* kp = &Ks[(r * 8 + j) * 128 + soff];
        uint4 u0 = *(const uint4*)kp;
        uint4 u1 = *(const uint4*)(kp + 8);
        const __half2* h0 = (const __half2*)&u0;
        const __half2* h1 = (const __half2*)&u1;
        float d = 0.f;
        #pragma unroll
        for (int p = 0; p < 4; p++) {
            float2 f0 = __half22float2(h0[p]);
            float2 f1 = __half22float2(h1[p]);
            d += q[p * 2] * f0.x + q[p * 2 + 1] * f0.y;
            d += q[8 + p * 2] * f1.x + q[8 + p * 2 + 1] * f1.y;
        }
        d += __shfl_xor_sync(0xffffffffu, d, 1);
        lg[j] = (j == i) ? -1e9f : d * 0.17677669529663687f;
    }
    float m = lg[0];
    #pragma unroll
    for (int j = 1; j < 8; j++) m = fmaxf(m, lg[j]);
    float ssum = 0.f;
    #pragma unroll
    for (int j = 0; j < 8; j++) { lg[j] = __expf(lg[j] - m); ssum += lg[j]; }
    float inv = 1.f / ssum;

    float acc[16];
    #pragma unroll
    for (int dd = 0; dd < 16; dd++) acc[dd] = 0.f;
    #pragma unroll
    for (int j = 0; j < 8; j++) {
        float p = lg[j] * inv;
        const __half* vp = &Vs[(r * 8 + j) * 128 + soff];
        uint4 u0 = *(const uint4*)vp;
        uint4 u1 = *(const uint4*)(vp + 8);
        const __half2* h0 = (const __half2*)&u0;
        const __half2* h1 = (const __half2*)&u1;
        #pragma unroll
        for (int pp = 0; pp < 4; pp++) {
            float2 f0 = __half22float2(h0[pp]);
            float2 f1 = __half22float2(h1[pp]);
            acc[pp * 2]     += p * f0.x;
            acc[pp * 2 + 1] += p * f0.y;
            acc[8 + pp * 2]     += p * f1.x;
            acc[8 + pp * 2 + 1] += p * f1.y;
        }
    }
    {
        uint4 u0, u1;
        unsigned* w0 = (unsigned*)&u0;
        unsigned* w1 = (unsigned*)&u1;
        #pragma unroll
        for (int p = 0; p < 4; p++) {
            w0[p] = pkh2(acc[p * 2], acc[p * 2 + 1]);
            w1[p] = pkh2(acc[8 + p * 2], acc[8 + p * 2 + 1]);
        }
        *(uint4*)(g_oth + base)     = u0;
        *(uint4*)(g_oth + base + 8) = u1;
    }
}

// ---------------- launch -----------------------------------------------------------
extern "C" void kernel_launch(void* const* d_in, const int* in_sizes, int n_in,
                              void* d_out, int out_size)
{
    const float* states  = (const float*)d_in[0];
    const float* actions = (const float*)d_in[1];
    const float* We      = (const float*)d_in[2];
    const float* be      = (const float*)d_in[3];
    const float* Wse     = (const float*)d_in[4];
    const float* bs      = (const float*)d_in[5];
    const float* Wk      = (const float*)d_in[6];
    const float* Wq      = (const float*)d_in[7];
    const float* Wv      = (const float*)d_in[8];
    const float* bv      = (const float*)d_in[9];
    const float* Wc1     = (const float*)d_in[10];
    const float* bc1     = (const float*)d_in[11];
    const float* Wc2     = (const float*)d_in[12];
    const float* bc2     = (const float*)d_in[13];
    float* out = (float*)d_out;

    size_t ncvt = (size_t)NAG * BATCH * (SDIM + ADIM) / 8;
    size_t nw   = (size_t)NAG * 128 * 144 + NAG * 128 * 128 + 3 * 128 * 128
                + (size_t)NAG * 128 * 256;
    size_t ntot = ncvt + nw;
    prep_all<<<(unsigned)((ntot + 255) / 256), 256>>>(states, actions, We, Wse,
                                                      Wk, Wq, Wv, Wc1);

    enc_kernel<<<dim3(BATCH / 128, 2, NAG), 256>>>(be, bs);
    kqv_kernel<<<dim3(BATCH / 128, 3, NAG), 256>>>(bv);
    attn_kernel<<<BATCH / 4, 256>>>();
    critic16p<<<dim3(BATCH / 128, 1, NAG), 256>>>(actions, bc1, Wc2, bc2, out);
}

// round 15
// speedup vs baseline: 1.4244x; 1.0430x over previous
#include <cuda_runtime.h>
#include <cuda_fp16.h>
#include <cstdint>

#define NAG   8
#define BATCH 32768
#define SDIM  128
#define ADIM  16
#define HID   128
#define HEADS 4
#define AD    32

// ---------------- scratch (device globals; no allocation allowed) ----------------
__device__ __half g_sa [(size_t)NAG * BATCH * HID];
__device__ __half g_se [(size_t)NAG * BATCH * HID];
__device__ __half g_Kb [(size_t)NAG * BATCH * HID];
__device__ __half g_Qb [(size_t)NAG * BATCH * HID];
__device__ __half g_Vb [(size_t)NAG * BATCH * HID];
__device__ __half g_oth[(size_t)NAG * BATCH * HID];
__device__ __half g_sth[(size_t)NAG * BATCH * SDIM];
__device__ __half g_ach[(size_t)NAG * BATCH * ADIM];
__device__ __half g_Wet [NAG * 128 * 144];
__device__ __half g_Wst [NAG * 128 * 128];
__device__ __half g_Wkt [128 * 128];
__device__ __half g_Wqt [128 * 128];
__device__ __half g_Wvt [128 * 128];
__device__ __half g_Wc1t[NAG * 128 * 256];

__device__ __forceinline__ unsigned pkh2(float a, float b) {
    __half2 h = __floats2half2_rn(a, b);
    return *(unsigned*)&h;
}

#define SROW 12          // 8 data words (16 halves) + 4 pad; frag banks bijective
#define TW   (128 * SROW)  // words per k16 tile (A or B)
#define MT   4           // m-tiles per CTA (weight-resident GEMMs)
#define CSTG 3           // critic pipeline stages

#define MMA16(acc, a0, a1, a2, a3, b0, b1)                                        \
    asm("mma.sync.aligned.m16n8k16.row.col.f32.f16.f16.f32 "                      \
        "{%0,%1,%2,%3}, {%4,%5,%6,%7}, {%8,%9}, {%0,%1,%2,%3};"                   \
        : "+f"((acc)[0]), "+f"((acc)[1]), "+f"((acc)[2]), "+f"((acc)[3])          \
        : "r"(a0), "r"(a1), "r"(a2), "r"(a3), "r"(b0), "r"(b1))

#define CPA16(dst, src) \
    asm volatile("cp.async.cg.shared.global [%0], [%1], 16;\n" :: "r"(dst), "l"(src))
#define CP_COMMIT()  asm volatile("cp.async.commit_group;\n")
#define CP_WAIT2()   asm volatile("cp.async.wait_group 2;\n")
#define CP_WAIT1()   asm volatile("cp.async.wait_group 1;\n")
#define CP_WAIT0()   asm volatile("cp.async.wait_group 0;\n")

// ---------------- merged prep: input fp16 copies + transposed fp16 weights ---------
__global__ void prep_all(const float* __restrict__ states,
                         const float* __restrict__ actions,
                         const float* __restrict__ We, const float* __restrict__ Ws,
                         const float* __restrict__ Wk, const float* __restrict__ Wq,
                         const float* __restrict__ Wv, const float* __restrict__ Wc1)
{
    size_t i  = (size_t)blockIdx.x * blockDim.x + threadIdx.x;
    size_t ns = (size_t)NAG * BATCH * SDIM / 8;
    size_t na = (size_t)NAG * BATCH * ADIM / 8;
    if (i < ns) {
        const float4* s = (const float4*)states + i * 2;
        float4 a = s[0], b = s[1];
        uint4 u = { pkh2(a.x, a.y), pkh2(a.z, a.w), pkh2(b.x, b.y), pkh2(b.z, b.w) };
        *(uint4*)(g_sth + i * 8) = u;
        return;
    }
    if (i < ns + na) {
        size_t j = i - ns;
        const float4* s = (const float4*)actions + j * 2;
        float4 a = s[0], b = s[1];
        uint4 u = { pkh2(a.x, a.y), pkh2(a.z, a.w), pkh2(b.x, b.y), pkh2(b.z, b.w) };
        *(uint4*)(g_ach + j * 8) = u;
        return;
    }
    long w = (long)(i - ns - na);
    const int nWe = NAG * 128 * 144;
    const int nWs = NAG * 128 * 128;
    const int nH  = 128 * 128;
    const int nWc = NAG * 128 * 256;
    if (w < 0 || w >= nWe + nWs + 3 * nH + nWc) return;
    int iw = (int)w;
    if (iw < nWe) {
        int n = iw / (128 * 144), r = iw % (128 * 144);
        int c = r / 144, k = r % 144;
        g_Wet[iw] = __float2half_rn(We[((size_t)n * 144 + k) * 128 + c]);
    } else if (iw < nWe + nWs) {
        int j = iw - nWe;
        int n = j / (128 * 128), r = j % (128 * 128);
        int c = r / 128, k = r % 128;
        g_Wst[j] = __float2half_rn(Ws[((size_t)n * 128 + k) * 128 + c]);
    } else if (iw < nWe + nWs + 3 * nH) {
        int j = iw - nWe - nWs;
        int which = j / nH, r = j % nH;
        int c = r / 128, k = r % 128;
        const float* W = which == 0 ? Wk : (which == 1 ? Wq : Wv);
        __half* D = which == 0 ? g_Wkt : (which == 1 ? g_Wqt : g_Wvt);
        D[r] = __float2half_rn(W[(size_t)(c >> 5) * (HID * AD) + (size_t)k * AD + (c & 31)]);
    } else {
        int j = iw - nWe - nWs - 3 * nH;
        int n = j / (128 * 256), r = j % (128 * 256);
        int c = r / 256, k = r % 256;
        g_Wc1t[j] = __float2half_rn(Wc1[((size_t)n * 256 + k) * 128 + c]);
    }
}

// ---------------- weight-resident multi-m-tile GEMM core ---------------------------
// B (full [128 n][Ktot k]) resident in smem (1 commit group); MT m-tiles processed
// with a continuous 4-stage A ring over global tile index g. Dynamic smem:
// [A: 4*TW words][B: nkt*TW words].
__device__ __forceinline__ void gemm_multi(
    const __half* A1n, int a1w, const __half* A2n, int a2w,
    const __half* Wtn, int Ktot,
    const float* bn, int dorelu, __half* Cn,
    unsigned* sm, int b0g)
{
    int tid = threadIdx.x;
    int wid = tid >> 5, lane = tid & 31;
    int grp = lane >> 2, tig = lane & 3;
    int wm  = (wid >> 2) * 64;
    int wn  = (wid & 3) * 32;
    int am  = tid >> 1, ahs = tid & 1;
    int nkt = Ktot >> 4;

    unsigned* Ast  = sm;
    unsigned* Bres = sm + 4 * TW;
    uint32_t sA  = (uint32_t)__cvta_generic_to_shared(Ast);
    uint32_t sBr = (uint32_t)__cvta_generic_to_shared(Bres);
    uint32_t sOff = (am * SROW + ahs * 4) * 4;

    // ---- resident B: all k-tiles, one commit group ----
    {
        const __half* bRow = Wtn + (size_t)am * Ktot + ahs * 8;
        for (int t = 0; t < nkt; t++)
            CPA16(sBr + t * (TW * 4) + sOff, bRow + t * 16);
        CP_COMMIT();
    }

    // ---- A fill for global tile g (m-tile fmt, k-tile fkt tracked by caller) ----
    auto fillA = [&](int g, int fmt, int fkt) {
        int k = fkt * 16 + ahs * 8;
        int row = b0g + fmt * 128 + am;
        const __half* asrc = (k < a1w)
            ? A1n + (size_t)row * a1w + k
            : A2n + (size_t)row * a2w + (k - a1w);
        CPA16(sA + (g & 3) * (TW * 4) + sOff, asrc);
        CP_COMMIT();
    };

    int G = MT * nkt;
    // prologue fills g = 0,1,2 (all within m-tile 0 since nkt >= 3)
    fillA(0, 0, 0); fillA(1, 0, 1); fillA(2, 0, 2);

    float acc[4][4][4];
    #pragma unroll
    for (int mt = 0; mt < 4; mt++)
        #pragma unroll
        for (int nt = 0; nt < 4; nt++)
            #pragma unroll
            for (int r = 0; r < 4; r++) acc[mt][nt][r] = 0.f;

    int kt = 0, mt = 0;            // compute-cursor
    int fkt = 3, fmt = 0;          // fill-cursor (next fill = g+3)
    if (fkt >= nkt) { fkt -= nkt; fmt++; }

    for (int g = 0; g < G; g++) {
        int rem = G - 1 - g;
        if (rem >= 2)      { CP_WAIT2(); }
        else if (rem == 1) { CP_WAIT1(); }
        else               { CP_WAIT0(); }
        __syncthreads();

        const unsigned* Ab = Ast + (g & 3) * TW;
        const unsigned* Bb = Bres + kt * TW;
        unsigned af[4][4];
        #pragma unroll
        for (int t = 0; t < 4; t++) {
            int m = wm + t * 16 + grp;
            af[t][0] = Ab[m * SROW + tig];
            af[t][1] = Ab[(m + 8) * SROW + tig];
            af[t][2] = Ab[m * SROW + tig + 4];
            af[t][3] = Ab[(m + 8) * SROW + tig + 4];
        }
        unsigned bf[4][2];
        #pragma unroll
        for (int t = 0; t < 4; t++) {
            int c = wn + t * 8 + grp;
            bf[t][0] = Bb[c * SROW + tig];
            bf[t][1] = Bb[c * SROW + tig + 4];
        }
        #pragma unroll
        for (int t = 0; t < 4; t++)
            #pragma unroll
            for (int u = 0; u < 4; u++)
                MMA16(acc[t][u], af[t][0], af[t][1], af[t][2], af[t][3],
                      bf[u][0], bf[u][1]);

        if (g + 3 < G) {
            fillA(g + 3, fmt, fkt);
            if (++fkt == nkt) { fkt = 0; fmt++; }
        }

        if (++kt == nkt) {
            // ---- epilogue for m-tile mt ----
            int rbase = b0g + mt * 128;
            #pragma unroll
            for (int u = 0; u < 4; u++) {
                int col = wn + u * 8 + tig * 2;
                float bj0 = bn ? bn[col]     : 0.f;
                float bj1 = bn ? bn[col + 1] : 0.f;
                #pragma unroll
                for (int t = 0; t < 4; t++) {
                    int row0 = rbase + wm + t * 16 + grp;
                    float v0 = acc[t][u][0] + bj0;
                    float v1 = acc[t][u][1] + bj1;
                    float v2 = acc[t][u][2] + bj0;
                    float v3 = acc[t][u][3] + bj1;
                    if (dorelu) {
                        v0 = fmaxf(v0, 0.f); v1 = fmaxf(v1, 0.f);
                        v2 = fmaxf(v2, 0.f); v3 = fmaxf(v3, 0.f);
                    }
                    *(__half2*)&Cn[(size_t)row0 * 128 + col]       = __floats2half2_rn(v0, v1);
                    *(__half2*)&Cn[(size_t)(row0 + 8) * 128 + col] = __floats2half2_rn(v2, v3);
                    acc[t][u][0] = 0.f; acc[t][u][1] = 0.f;
                    acc[t][u][2] = 0.f; acc[t][u][3] = 0.f;
                }
            }
            kt = 0; mt++;
        }
    }
}

// ---------------- merged encoder launch: y=0 -> sa_enc (K=144), y=1 -> s_enc -------
__global__ void __launch_bounds__(256)
enc_kernel(const float* __restrict__ be, const float* __restrict__ bs)
{
    extern __shared__ unsigned smdyn[];
    int n = blockIdx.z, b0g = blockIdx.x * (128 * MT);
    const __half* sthn = g_sth + (size_t)n * BATCH * SDIM;
    if (blockIdx.y == 0) {
        gemm_multi(sthn, SDIM, g_ach + (size_t)n * BATCH * ADIM, ADIM,
                   g_Wet + (size_t)n * 128 * 144, 144,
                   be + n * 128, 1, g_sa + (size_t)n * BATCH * 128, smdyn, b0g);
    } else {
        gemm_multi(sthn, SDIM, sthn, SDIM,
                   g_Wst + (size_t)n * 128 * 128, 128,
                   bs + n * 128, 1, g_se + (size_t)n * BATCH * 128, smdyn, b0g);
    }
}

// ---------------- merged K/Q/V launch: y=0 K, y=1 Q, y=2 V --------------------------
__global__ void __launch_bounds__(256)
kqv_kernel(const float* __restrict__ bv)
{
    extern __shared__ unsigned smdyn[];
    int n = blockIdx.z, b0g = blockIdx.x * (128 * MT);
    const __half* san = g_sa + (size_t)n * BATCH * 128;
    const __half* sen = g_se + (size_t)n * BATCH * 128;
    if (blockIdx.y == 0) {
        gemm_multi(san, HID, san, HID, g_Wkt, 128,
                   nullptr, 0, g_Kb + (size_t)n * BATCH * 128, smdyn, b0g);
    } else if (blockIdx.y == 1) {
        gemm_multi(sen, HID, sen, HID, g_Wqt, 128,
                   nullptr, 0, g_Qb + (size_t)n * BATCH * 128, smdyn, b0g);
    } else {
        gemm_multi(san, HID, san, HID, g_Wvt, 128,
                   bv, 1, g_Vb + (size_t)n * BATCH * 128, smdyn, b0g);
    }
}

// ---------------- pipelined fused critic (3 stages; R12/R14 proven) ----------------
__global__ void __launch_bounds__(256)
critic16p(const float* __restrict__ actions,
          const float* __restrict__ bc1, const float* __restrict__ Wc2,
          const float* __restrict__ bc2, float* __restrict__ out)
{
    __shared__ __align__(16) unsigned As[CSTG][TW];
    __shared__ __align__(16) unsigned Bs[CSTG][TW];
    __shared__ float Wc2s[128 * 16];
    __shared__ float bc1s[128];
    __shared__ float bc2s[16];
    __shared__ float rowacc[128];
    __shared__ int   amaxs[128];

    int n   = blockIdx.z;
    int b0g = blockIdx.x * 128;
    int tid = threadIdx.x;
    int wid = tid >> 5, lane = tid & 31;
    int grp = lane >> 2, tig = lane & 3;
    int wm  = (wid >> 2) * 64;
    int wn  = (wid & 3) * 32;
    int am  = tid >> 1, ahs = tid & 1;

    const __half* A1n = g_se  + (size_t)n * BATCH * 128;
    const __half* A2n = g_oth + (size_t)n * BATCH * 128;
    const __half* Wtn = g_Wc1t + (size_t)n * 128 * 256;
    const float*  Wc2n = Wc2 + (size_t)n * 128 * 16;

    #pragma unroll
    for (int t = 0; t < 2; t++) {
        int f = tid + t * 256;
        *(float4*)&Wc2s[f * 4] = *(const float4*)&Wc2n[f * 4];
    }
    if (tid < 128) {
        bc1s[tid] = bc1[n * 128 + tid];
        rowacc[tid] = 0.f;
        const float* ap = actions + ((size_t)n * BATCH + b0g + tid) * 16;
        float best = ap[0]; int bi = 0;
        #pragma unroll
        for (int c = 1; c < 16; c++) { float v = ap[c]; if (v > best) { best = v; bi = c; } }
        amaxs[tid] = bi;
    }
    if (tid < 16) bc2s[tid] = bc2[n * 16 + tid];

    uint32_t sA = (uint32_t)__cvta_generic_to_shared(&As[0][0]);
    uint32_t sB = (uint32_t)__cvta_generic_to_shared(&Bs[0][0]);
    uint32_t sOff = (am * SROW + ahs * 4) * 4;
    const __half* bRow = Wtn + (size_t)am * 256;

    auto fill = [&](int kt) {
        int s = kt % CSTG;
        int k = kt * 16 + ahs * 8;
        const __half* asrc = (k < 128) ? (A1n + (size_t)(b0g + am) * 128 + k)
                                       : (A2n + (size_t)(b0g + am) * 128 + (k - 128));
        CPA16(sA + s * (TW * 4) + sOff, asrc);
        CPA16(sB + s * (TW * 4) + sOff, bRow + k);
        CP_COMMIT();
    };

    float acc[4][4][4];
    #pragma unroll
    for (int mt = 0; mt < 4; mt++)
        #pragma unroll
        for (int nt = 0; nt < 4; nt++)
            #pragma unroll
            for (int r = 0; r < 4; r++) acc[mt][nt][r] = 0.f;

    const int nkt = 16;
    fill(0);
    fill(1);

    for (int kt = 0; kt < nkt; kt++) {
        if (kt + 1 < nkt) { CP_WAIT1(); } else { CP_WAIT0(); }
        __syncthreads();
        const unsigned* Ab = As[kt % CSTG];
        const unsigned* Bb = Bs[kt % CSTG];
        unsigned af[4][4];
        #pragma unroll
        for (int mt = 0; mt < 4; mt++) {
            int m = wm + mt * 16 + grp;
            af[mt][0] = Ab[m * SROW + tig];
            af[mt][1] = Ab[(m + 8) * SROW + tig];
            af[mt][2] = Ab[m * SROW + tig + 4];
            af[mt][3] = Ab[(m + 8) * SROW + tig + 4];
        }
        unsigned bf[4][2];
        #pragma unroll
        for (int nt = 0; nt < 4; nt++) {
            int c = wn + nt * 8 + grp;
            bf[nt][0] = Bb[c * SROW + tig];
            bf[nt][1] = Bb[c * SROW + tig + 4];
        }
        #pragma unroll
        for (int mt = 0; mt < 4; mt++)
            #pragma unroll
            for (int nt = 0; nt < 4; nt++)
                MMA16(acc[mt][nt], af[mt][0], af[mt][1], af[mt][2], af[mt][3],
                      bf[nt][0], bf[nt][1]);
        if (kt + 2 < nkt) fill(kt + 2);
    }

    #pragma unroll
    for (int mt = 0; mt < 4; mt++) {
        int row0 = wm + mt * 16 + grp;
        int a0 = amaxs[row0];
        int a1 = amaxs[row0 + 8];
        float p0 = 0.f, p1 = 0.f;
        #pragma unroll
        for (int nt = 0; nt < 4; nt++) {
            int col = wn + nt * 8 + tig * 2;
            float bj0 = bc1s[col], bj1 = bc1s[col + 1];
            float h00 = fmaxf(acc[mt][nt][0] + bj0, 0.f);
            float h01 = fmaxf(acc[mt][nt][1] + bj1, 0.f);
            float h10 = fmaxf(acc[mt][nt][2] + bj0, 0.f);
            float h11 = fmaxf(acc[mt][nt][3] + bj1, 0.f);
            p0 += h00 * Wc2s[col * 16 + a0] + h01 * Wc2s[(col + 1) * 16 + a0];
            p1 += h10 * Wc2s[col * 16 + a1] + h11 * Wc2s[(col + 1) * 16 + a1];
        }
        p0 += __shfl_xor_sync(0xffffffffu, p0, 1);
        p0 += __shfl_xor_sync(0xffffffffu, p0, 2);
        p1 += __shfl_xor_sync(0xffffffffu, p1, 1);
        p1 += __shfl_xor_sync(0xffffffffu, p1, 2);
        if (tig == 0) {
            atomicAdd(&rowacc[row0], p0);
            atomicAdd(&rowacc[row0 + 8], p1);
        }
    }
    __syncthreads();
    if (tid < 128)
        out[(size_t)n * BATCH + b0g + tid] = rowacc[tid] + bc2s[amaxs[tid]];
}

// ---------------- attention: fp16 smem staging, fp32 math (R14 proven) -------------
__global__ void __launch_bounds__(256)
attn_kernel()
{
    __shared__ __align__(16) __half Ks[4 * 8 * 128];
    __shared__ __align__(16) __half Vs[4 * 8 * 128];
    int tid = threadIdx.x;
    int b0  = blockIdx.x * 4;

    #pragma unroll
    for (int t = 0; t < 2; t++) {
        int f  = tid + t * 256;
        int c8 = f & 15;
        int rj = f >> 4;
        int r  = rj & 3, j = rj >> 2;
        size_t g = ((size_t)j * BATCH + b0 + r) * 128 + c8 * 8;
        int s = (r * 8 + j) * 128 + c8 * 8;
        *(uint4*)(Ks + s) = *(const uint4*)(g_Kb + g);
        *(uint4*)(Vs + s) = *(const uint4*)(g_Vb + g);
    }
    __syncthreads();

    int hf = tid & 1;
    int i  = (tid >> 1) & 7;
    int k  = (tid >> 4) & 3;
    int r  = tid >> 6;

    float q[16];
    size_t base = ((size_t)i * BATCH + b0 + r) * 128 + k * 32 + hf * 16;
    {
        uint4 u0 = *(const uint4*)(g_Qb + base);
        uint4 u1 = *(const uint4*)(g_Qb + base + 8);
        const __half2* h0 = (const __half2*)&u0;
        const __half2* h1 = (const __half2*)&u1;
        #pragma unroll
        for (int p = 0; p < 4; p++) {
            float2 f0 = __half22float2(h0[p]);
            float2 f1 = __half22float2(h1[p]);
            q[p * 2] = f0.x; q[p * 2 + 1] = f0.y;
            q[8 + p * 2] = f1.x; q[8 + p * 2 + 1] = f1.y;
        }
    }

    int soff = k * 32 + hf * 16;
    float lg[8];
    #pragma unroll
    for (int j = 0; j < 8; j++) {
        const __half* kp = &Ks[(r * 8 + j) * 128 + soff];
        uint4 u0 = *(const uint4*)kp;
        uint4 u1 = *(const uint4*)(kp + 8);
        const __half2* h0 = (const __half2*)&u0;
        const __half2* h1 = (const __half2*)&u1;
        float d = 0.f;
        #pragma unroll
        for (int p = 0; p < 4; p++) {
            float2 f0 = __half22float2(h0[p]);
            float2 f1 = __half22float2(h1[p]);
            d += q[p * 2] * f0.x + q[p * 2 + 1] * f0.y;
            d += q[8 + p * 2] * f1.x + q[8 + p * 2 + 1] * f1.y;
        }
        d += __shfl_xor_sync(0xffffffffu, d, 1);
        lg[j] = (j == i) ? -1e9f : d * 0.17677669529663687f;
    }
    float m = lg[0];
    #pragma unroll
    for (int j = 1; j < 8; j++) m = fmaxf(m, lg[j]);
    float ssum = 0.f;
    #pragma unroll
    for (int j = 0; j < 8; j++) { lg[j] = __expf(lg[j] - m); ssum += lg[j]; }
    float inv = 1.f / ssum;

    float acc[16];
    #pragma unroll
    for (int dd = 0; dd < 16; dd++) acc[dd] = 0.f;
    #pragma unroll
    for (int j = 0; j < 8; j++) {
        float p = lg[j] * inv;
        const __half* vp = &Vs[(r * 8 + j) * 128 + soff];
        uint4 u0 = *(const uint4*)vp;
        uint4 u1 = *(const uint4*)(vp + 8);
        const __half2* h0 = (const __half2*)&u0;
        const __half2* h1 = (const __half2*)&u1;
        #pragma unroll
        for (int pp = 0; pp < 4; pp++) {
            float2 f0 = __half22float2(h0[pp]);
            float2 f1 = __half22float2(h1[pp]);
            acc[pp * 2]     += p * f0.x;
            acc[pp * 2 + 1] += p * f0.y;
            acc[8 + pp * 2]     += p * f1.x;
            acc[8 + pp * 2 + 1] += p * f1.y;
        }
    }
    {
        uint4 u0, u1;
        unsigned* w0 = (unsigned*)&u0;
        unsigned* w1 = (unsigned*)&u1;
        #pragma unroll
        for (int p = 0; p < 4; p++) {
            w0[p] = pkh2(acc[p * 2], acc[p * 2 + 1]);
            w1[p] = pkh2(acc[8 + p * 2], acc[8 + p * 2 + 1]);
        }
        *(uint4*)(g_oth + base)     = u0;
        *(uint4*)(g_oth + base + 8) = u1;
    }
}

// ---------------- launch -----------------------------------------------------------
extern "C" void kernel_launch(void* const* d_in, const int* in_sizes, int n_in,
                              void* d_out, int out_size)
{
    const float* states  = (const float*)d_in[0];
    const float* actions = (const float*)d_in[1];
    const float* We      = (const float*)d_in[2];
    const float* be      = (const float*)d_in[3];
    const float* Wse     = (const float*)d_in[4];
    const float* bs      = (const float*)d_in[5];
    const float* Wk      = (const float*)d_in[6];
    const float* Wq      = (const float*)d_in[7];
    const float* Wv      = (const float*)d_in[8];
    const float* bv      = (const float*)d_in[9];
    const float* Wc1     = (const float*)d_in[10];
    const float* bc1     = (const float*)d_in[11];
    const float* Wc2     = (const float*)d_in[12];
    const float* bc2     = (const float*)d_in[13];
    float* out = (float*)d_out;

    // dynamic smem opt-in (idempotent; no stream work — capture-safe)
    static int attr_done = 0;
    const int enc_smem = (4 + 9) * TW * 4;   // 79,872 B (K=144 worst case)
    const int kqv_smem = (4 + 8) * TW * 4;   // 73,728 B
    if (!attr_done) {
        cudaFuncSetAttribute(enc_kernel, cudaFuncAttributeMaxDynamicSharedMemorySize, enc_smem);
        cudaFuncSetAttribute(kqv_kernel, cudaFuncAttributeMaxDynamicSharedMemorySize, kqv_smem);
        attr_done = 1;
    }

    size_t ncvt = (size_t)NAG * BATCH * (SDIM + ADIM) / 8;
    size_t nw   = (size_t)NAG * 128 * 144 + NAG * 128 * 128 + 3 * 128 * 128
                + (size_t)NAG * 128 * 256;
    size_t ntot = ncvt + nw;
    prep_all<<<(unsigned)((ntot + 255) / 256), 256>>>(states, actions, We, Wse,
                                                      Wk, Wq, Wv, Wc1);

    enc_kernel<<<dim3(BATCH / (128 * MT), 2, NAG), 256, enc_smem>>>(be, bs);
    kqv_kernel<<<dim3(BATCH / (128 * MT), 3, NAG), 256, kqv_smem>>>(bv);
    attn_kernel<<<BATCH / 4, 256>>>();
    critic16p<<<dim3(BATCH / 128, 1, NAG), 256>>>(actions, bc1, Wc2, bc2, out);
}